// round 9
// baseline (speedup 1.0000x reference)
#include <cuda_runtime.h>
#include <stdint.h>
#include <math.h>

// TopkMoeFFN: N=131072, H=128, O=128, E=8, top2, fp32.
// zero -> gate (atomic slot alloc) -> ffn x2 (warp-specialized).
// k_ffn: producer warps (gather+convert, double-buffered A) feed
// consumer warps (128x128x128 bf16-split mma.sync GEMM + epilogue)
// via named barriers.

#define NTOK  131072
#define HDIM  128
#define ODIM  128
#define NEXP  8
#define NBLK  1024
#define GRID3 152
#define WPITCH 272
#define LODELTA 34816u

__device__ float4 g_meta[NTOK];
__device__ int g_cnt[2][NEXP];
__device__ unsigned int g_etok[2][NEXP * NTOK];
__device__ float g_egat[2][NEXP * NTOK];

__device__ __forceinline__ uint32_t smem_u32(const void* p) {
    uint32_t a;
    asm("{ .reg .u64 t; cvta.to.shared.u64 t, %1; cvt.u32.u64 %0, t; }"
        : "=r"(a) : "l"(p));
    return a;
}

__device__ __forceinline__ uint32_t cvt_bf16x2(float hi, float lo) {
    uint32_t d;
    asm("cvt.rn.bf16x2.f32 %0, %1, %2;" : "=r"(d) : "f"(hi), "f"(lo));
    return d;
}

__device__ __forceinline__ void split2(float f0, float f1,
                                       uint32_t& hi, uint32_t& lo) {
    hi = cvt_bf16x2(f1, f0);
    float h0 = __uint_as_float(hi << 16);
    float h1 = __uint_as_float(hi & 0xffff0000u);
    lo = cvt_bf16x2(f1 - h1, f0 - h0);
}

__device__ __forceinline__ void ldsm_x4t(uint32_t& r0, uint32_t& r1,
                                         uint32_t& r2, uint32_t& r3, uint32_t a) {
    asm volatile("ldmatrix.sync.aligned.m8n8.x4.trans.shared.b16 {%0,%1,%2,%3}, [%4];"
                 : "=r"(r0), "=r"(r1), "=r"(r2), "=r"(r3) : "r"(a));
}

__device__ __forceinline__ void ldsm_x4(uint32_t& r0, uint32_t& r1,
                                        uint32_t& r2, uint32_t& r3, uint32_t a) {
    asm volatile("ldmatrix.sync.aligned.m8n8.x4.shared.b16 {%0,%1,%2,%3}, [%4];"
                 : "=r"(r0), "=r"(r1), "=r"(r2), "=r"(r3) : "r"(a));
}

__device__ __forceinline__ void mma16816(float* c,
                                         uint32_t a0, uint32_t a1, uint32_t a2,
                                         uint32_t a3, uint32_t b0, uint32_t b1) {
    asm volatile(
        "mma.sync.aligned.m16n8k16.row.col.f32.bf16.bf16.f32 "
        "{%0,%1,%2,%3}, {%4,%5,%6,%7}, {%8,%9}, {%0,%1,%2,%3};"
        : "+f"(c[0]), "+f"(c[1]), "+f"(c[2]), "+f"(c[3])
        : "r"(a0), "r"(a1), "r"(a2), "r"(a3), "r"(b0), "r"(b1));
}

#define BAR_SYNC(id, cnt) \
    asm volatile("bar.sync %0, %1;" :: "r"(id), "r"(cnt) : "memory")
#define BAR_ARRIVE(id, cnt) \
    asm volatile("bar.arrive %0, %1;" :: "r"(id), "r"(cnt) : "memory")

// ---------------- kernel 0: zero counters ----------------
__global__ void k_zero() {
    if (threadIdx.x < 16) ((int*)g_cnt)[threadIdx.x] = 0;
}

// ---------------- kernel 1: gating + atomic slot allocation ----------------
#define G_SX   0
#define G_SWG  (128 * 132 * 4)
#define G_SMEM (G_SWG + HDIM * NEXP * 4)

extern __shared__ char smraw[];

__global__ void __launch_bounds__(128)
k_gate(const float* __restrict__ x, const float* __restrict__ wg) {
    float* sx  = (float*)(smraw + G_SX);
    float* swg = (float*)(smraw + G_SWG);
    __shared__ int wh0[4][8], wh1[4][8];
    __shared__ int gb0[8], gb1[8];

    const int tid = threadIdx.x, lane = tid & 31, w = tid >> 5;
    const int blk = blockIdx.x, tok0 = blk * 128;

    for (int i = tid; i < HDIM * NEXP; i += 128) swg[i] = wg[i];
    const float4* xg = (const float4*)(x + (size_t)tok0 * HDIM);
    for (int i = tid; i < 128 * 32; i += 128) {
        float4 v = xg[i];
        int t = i >> 5, c = (i & 31) * 4;
        *(float4*)(sx + t * 132 + c) = v;
    }
    __syncthreads();

    float lg[NEXP];
#pragma unroll
    for (int e = 0; e < NEXP; e++) lg[e] = 0.f;
    const float* xr = sx + tid * 132;
#pragma unroll 4
    for (int h4 = 0; h4 < 32; h4++) {
        float4 xq = *(const float4*)(xr + h4 * 4);
        const float* wr = swg + h4 * 32;
#pragma unroll
        for (int j = 0; j < 4; j++) {
            float xv = (j == 0) ? xq.x : (j == 1) ? xq.y : (j == 2) ? xq.z : xq.w;
            float4 wa = *(const float4*)(wr + j * 8);
            float4 wb = *(const float4*)(wr + j * 8 + 4);
            lg[0] = fmaf(xv, wa.x, lg[0]); lg[1] = fmaf(xv, wa.y, lg[1]);
            lg[2] = fmaf(xv, wa.z, lg[2]); lg[3] = fmaf(xv, wa.w, lg[3]);
            lg[4] = fmaf(xv, wb.x, lg[4]); lg[5] = fmaf(xv, wb.y, lg[5]);
            lg[6] = fmaf(xv, wb.z, lg[6]); lg[7] = fmaf(xv, wb.w, lg[7]);
        }
    }
    int i0 = 0; float v0 = lg[0];
#pragma unroll
    for (int e = 1; e < NEXP; e++)
        if (lg[e] > v0) { v0 = lg[e]; i0 = e; }
    int i1 = -1; float v1 = -3.4e38f;
#pragma unroll
    for (int e = 0; e < NEXP; e++)
        if (e != i0 && lg[e] > v1) { v1 = lg[e]; i1 = e; }
    float e1 = expf(v1 - v0);
    float g0 = 1.f / (1.f + e1);
    float g1 = e1 * g0;

    unsigned ltm = (1u << lane) - 1u;
    int myr0 = 0, myr1 = 0;
#pragma unroll
    for (int e = 0; e < NEXP; e++) {
        unsigned m0 = __ballot_sync(0xffffffffu, i0 == e);
        unsigned m1 = __ballot_sync(0xffffffffu, i1 == e);
        if (i0 == e) myr0 = __popc(m0 & ltm);
        if (i1 == e) myr1 = __popc(m1 & ltm);
        if (lane == e) { wh0[w][e] = __popc(m0); wh1[w][e] = __popc(m1); }
    }
    __syncthreads();
    int r0 = myr0, r1 = myr1;
    for (int ww = 0; ww < w; ww++) { r0 += wh0[ww][i0]; r1 += wh1[ww][i1]; }

    if (tid < NEXP) {
        int c0 = wh0[0][tid] + wh0[1][tid] + wh0[2][tid] + wh0[3][tid];
        int c1 = wh1[0][tid] + wh1[1][tid] + wh1[2][tid] + wh1[3][tid];
        gb0[tid] = atomicAdd(&g_cnt[0][tid], c0);
        gb1[tid] = atomicAdd(&g_cnt[1][tid], c1);
    }
    __syncthreads();

    int token = tok0 + tid;
    int s0 = gb0[i0] + r0, s1 = gb1[i1] + r1;
    g_etok[0][i0 * NTOK + s0] = (unsigned)token;
    g_egat[0][i0 * NTOK + s0] = g0;
    g_etok[1][i1 * NTOK + s1] = (unsigned)token;
    g_egat[1][i1 * NTOK + s1] = g1;
    g_meta[token] = make_float4(
        __uint_as_float((unsigned)i0 | ((unsigned)i1 << 8)), g0, g1, 0.f);
}

// ---------------- kernel 2: warp-specialized FFN GEMM ----------------
#define F_WHI   0
#define F_WLO   34816
#define F_A0HI  69632
#define F_A0LO  104448
#define F_A1HI  139264
#define F_A1LO  174080
#define F_BIAS  208896
#define F_TOK   212992      // 2 x 128 int
#define F_META  214016      // 2 x 128 float4
#define F_SMEM  218112
#define NTHR_F 512
// named barriers: full0=1 full1=2 empty0=3 empty1=4 wbar=5 cbias=6

#define TILE_ELI(t, e_, li_) do { \
        e_ = 0; \
        _Pragma("unroll") \
        for (int k_ = 0; k_ < NEXP; k_++) if (tb[k_ + 1] <= (t)) e_ = k_ + 1; \
        li_ = (t) - tb[e_]; \
    } while (0)

__global__ void __launch_bounds__(NTHR_F, 1)
k_ffn(const float* __restrict__ x, const float* __restrict__ we,
      const float* __restrict__ be, float* __restrict__ out, int p) {
    const int tid = threadIdx.x, lane = tid & 31, w = tid >> 5;
    float* sbias = (float*)(smraw + F_BIAS);
    int* stok = (int*)(smraw + F_TOK);
    float4* smeta = (float4*)(smraw + F_META);
    const uint32_t su = smem_u32(smraw);

    const unsigned* tokl = g_etok[p];
    const float* gatel   = g_egat[p];

    int cnt[NEXP], tb[NEXP + 1];
    tb[0] = 0;
#pragma unroll
    for (int e = 0; e < NEXP; e++) {
        cnt[e] = g_cnt[p][e];
        tb[e + 1] = tb[e] + ((cnt[e] + 127) >> 7);
    }
    const int ntiles = tb[NEXP];
    const int t0 = (int)((long long)blockIdx.x * ntiles / GRID3);
    const int t1 = (int)((long long)(blockIdx.x + 1) * ntiles / GRID3);
    if (t0 >= t1) return;

    if (w < 8) {
        // ================= CONSUMERS =================
        for (int i = tid; i < NEXP * ODIM; i += 256) sbias[i] = be[i];
        BAR_SYNC(6, 256);           // consumer-only: bias visible

        // allow producers to fill both buffers + initial W
        BAR_ARRIVE(3, NTHR_F);
        BAR_ARRIVE(4, NTHR_F);
        BAR_ARRIVE(5, NTHR_F);

        const int mt = w >> 1, nh = w & 1;
        const int grp = lane >> 3;
        const int ar = (lane & 7) + ((grp & 1) ? 8 : 0);
        const int ac = (grp >> 1) * 8;
        const uint32_t a_off = (uint32_t)(mt * 32 + ar) * WPITCH
                             + (uint32_t)ac * 2;
        const uint32_t b_base = su + F_WHI + (uint32_t)(lane & 15) * WPITCH
                              + (uint32_t)nh * 128u + (uint32_t)(lane >> 4) * 16u;
        const int qr = lane >> 2, qk = (lane & 3) * 2;

        int e_cur, li_cur;
        TILE_ELI(t0, e_cur, li_cur);

        for (int t = t0; t < t1; t++) {
            const int e = e_cur, li = li_cur;
            const int valid = min(128, cnt[e] - li * 128);
            const int s = (t - t0) & 1;

            BAR_SYNC(1 + s, NTHR_F);   // A[s] + W ready

            const uint32_t a_hi = su + (s ? F_A1HI : F_A0HI) + a_off;
            float acc[2][8][4];
#pragma unroll
            for (int m = 0; m < 2; m++)
#pragma unroll
                for (int nt = 0; nt < 8; nt++)
#pragma unroll
                    for (int j = 0; j < 4; j++) acc[m][nt][j] = 0.f;

#pragma unroll
            for (int kb = 0; kb < 8; kb++) {
                uint32_t ah[2][4], al[2][4];
                uint32_t aa0 = a_hi + (uint32_t)kb * 32;
                uint32_t aa1 = aa0 + 16u * WPITCH;
                ldsm_x4(ah[0][0], ah[0][1], ah[0][2], ah[0][3], aa0);
                ldsm_x4(al[0][0], al[0][1], al[0][2], al[0][3], aa0 + LODELTA);
                ldsm_x4(ah[1][0], ah[1][1], ah[1][2], ah[1][3], aa1);
                ldsm_x4(al[1][0], al[1][1], al[1][2], al[1][3], aa1 + LODELTA);
                uint32_t bb = b_base + (uint32_t)kb * 16 * WPITCH;
#pragma unroll
                for (int pr = 0; pr < 4; pr++) {
                    uint32_t bh0, bh1, bh2, bh3, bl0, bl1, bl2, bl3;
                    ldsm_x4t(bh0, bh1, bh2, bh3, bb + pr * 32);
                    ldsm_x4t(bl0, bl1, bl2, bl3, bb + pr * 32 + LODELTA);
#pragma unroll
                    for (int m = 0; m < 2; m++) {
                        mma16816(acc[m][2 * pr], ah[m][0], ah[m][1], ah[m][2],
                                 ah[m][3], bh0, bh1);
                        mma16816(acc[m][2 * pr], ah[m][0], ah[m][1], ah[m][2],
                                 ah[m][3], bl0, bl1);
                        mma16816(acc[m][2 * pr], al[m][0], al[m][1], al[m][2],
                                 al[m][3], bh0, bh1);
                        mma16816(acc[m][2 * pr + 1], ah[m][0], ah[m][1], ah[m][2],
                                 ah[m][3], bh2, bh3);
                        mma16816(acc[m][2 * pr + 1], ah[m][0], ah[m][1], ah[m][2],
                                 ah[m][3], bl2, bl3);
                        mma16816(acc[m][2 * pr + 1], al[m][0], al[m][1], al[m][2],
                                 al[m][3], bh2, bh3);
                    }
                }
            }

            // epilogue
#pragma unroll
            for (int m = 0; m < 2; m++) {
#pragma unroll
                for (int hrow = 0; hrow < 2; hrow++) {
                    int r = mt * 32 + m * 16 + qr + hrow * 8;
                    if (r >= valid) continue;
                    int tk = stok[s * 128 + r];
                    float* op = out + (size_t)tk * ODIM;
                    const int ci = hrow * 2;
                    if (p == 0) {
                        float4 mm = smeta[s * 128 + r];
                        unsigned u = __float_as_uint(mm.x);
                        const float* b0p = sbias + (u & 0xff) * ODIM;
                        const float* b1p = sbias + ((u >> 8) & 0xff) * ODIM;
                        float gg0 = mm.y, gg1 = mm.z;
#pragma unroll
                        for (int nt = 0; nt < 8; nt++) {
                            int col = nh * 64 + nt * 8 + qk;
                            float2 v;
                            v.x = acc[m][nt][ci] + gg0 * b0p[col] + gg1 * b1p[col];
                            v.y = acc[m][nt][ci + 1]
                                + gg0 * b0p[col + 1] + gg1 * b1p[col + 1];
                            *(float2*)(op + col) = v;
                        }
                    } else {
                        float2 o[8];
#pragma unroll
                        for (int nt = 0; nt < 8; nt++)
                            o[nt] = *(float2*)(op + nh * 64 + nt * 8 + qk);
#pragma unroll
                        for (int nt = 0; nt < 8; nt++) {
                            int col = nh * 64 + nt * 8 + qk;
                            float2 v = o[nt];
                            v.x += acc[m][nt][ci];
                            v.y += acc[m][nt][ci + 1];
                            *(float2*)(op + col) = v;
                        }
                    }
                }
            }

            BAR_ARRIVE(3 + s, NTHR_F);   // A[s] free
            if (t + 1 < t1) {
                int en, lin;
                TILE_ELI(t + 1, en, lin);
                if (en != e) BAR_ARRIVE(5, NTHR_F);   // W may be replaced
                e_cur = en; li_cur = lin;
            }
        }
    } else {
        // ================= PRODUCERS =================
        const int ptid = tid - 256;
        const int row = ptid >> 1, half = ptid & 1;
        const uint32_t abase = (uint32_t)row * WPITCH + (uint32_t)half * 128u;

        int cur_e = -1;
        for (int t = t0; t < t1; t++) {
            int e, li;
            TILE_ELI(t, e, li);
            const int valid = min(128, cnt[e] - li * 128);
            const int lb = e * NTOK + li * 128;
            const int s = (t - t0) & 1;

            unsigned token = 0; float gv = 0.f;
            if (row < valid) { token = tokl[lb + row]; gv = gatel[lb + row]; }

            // issue x loads early (registers, no buffer hazard)
            float4 v[16];
            const float4* xr = (const float4*)(x + (size_t)token * HDIM
                                               + half * 64);
#pragma unroll
            for (int i = 0; i < 16; i++) v[i] = xr[i];

            if (e != cur_e) {
                BAR_SYNC(5, NTHR_F);     // consumers done with old W
                const float4* wgl = (const float4*)(we + (size_t)e * HDIM * ODIM);
#pragma unroll
                for (int i2 = 0; i2 < 16; i2++) {
                    int i = ptid + i2 * 256;
                    float4 wv = wgl[i];
                    int h = i >> 5, o4 = i & 31;
                    uint32_t h0, l0, h1, l1;
                    split2(wv.x, wv.y, h0, l0);
                    split2(wv.z, wv.w, h1, l1);
                    uint32_t off = (uint32_t)h * WPITCH + (uint32_t)o4 * 8;
                    *(uint2*)(smraw + F_WHI + off) = make_uint2(h0, h1);
                    *(uint2*)(smraw + F_WLO + off) = make_uint2(l0, l1);
                }
                cur_e = e;
            }

            BAR_SYNC(3 + s, NTHR_F);     // A[s] free

            if (half == 0) {
                stok[s * 128 + row] = (int)token;
                if (p == 0) smeta[s * 128 + row] = g_meta[token];
            }
            const uint32_t ab = su + (s ? F_A1HI : F_A0HI) + abase;
#pragma unroll
            for (int i = 0; i < 16; i += 2) {
                uint32_t h0, l0, h1, l1, h2, l2, h3, l3;
                split2(gv * v[i].x, gv * v[i].y, h0, l0);
                split2(gv * v[i].z, gv * v[i].w, h1, l1);
                split2(gv * v[i + 1].x, gv * v[i + 1].y, h2, l2);
                split2(gv * v[i + 1].z, gv * v[i + 1].w, h3, l3);
                *(uint4*)(smraw + (ab - su) + i * 8) = make_uint4(h0, h1, h2, h3);
                *(uint4*)(smraw + (ab - su) + LODELTA + i * 8) =
                    make_uint4(l0, l1, l2, l3);
            }

            BAR_ARRIVE(1 + s, NTHR_F);   // A[s] + W ready
        }
    }
}

// ---------------- launch ----------------
extern "C" void kernel_launch(void* const* d_in, const int* in_sizes, int n_in,
                              void* d_out, int out_size) {
    const float* x  = (const float*)d_in[0];
    const float* wg = (const float*)d_in[1];
    // d_in[2] = w_noise (inactive in eval mode)
    const float* we = (const float*)d_in[3];
    const float* be = (const float*)d_in[4];
    float* out = (float*)d_out;

    cudaFuncSetAttribute(k_gate, cudaFuncAttributeMaxDynamicSharedMemorySize,
                         G_SMEM);
    cudaFuncSetAttribute(k_ffn, cudaFuncAttributeMaxDynamicSharedMemorySize,
                         F_SMEM);

    k_zero<<<1, 32>>>();
    k_gate<<<NBLK, 128, G_SMEM>>>(x, wg);
    k_ffn<<<GRID3, NTHR_F, F_SMEM>>>(x, we, be, out, 0);
    k_ffn<<<GRID3, NTHR_F, F_SMEM>>>(x, we, be, out, 1);
}

// round 10
// speedup vs baseline: 1.4634x; 1.4634x over previous
#include <cuda_runtime.h>
#include <stdint.h>
#include <math.h>

// TopkMoeFFN: N=131072, H=128, O=128, E=8, top2, fp32.
// zero -> gate (atomic slot alloc) -> ffn x2 phases.
// k_ffn = round-6 proven pipeline: cp.async-staged A gather + convert,
// x2.trans B ldmatrix, 128x128x128 bf16-split mma.sync tiles.

#define NTOK  131072
#define HDIM  128
#define ODIM  128
#define NEXP  8
#define NBLK  1024
#define GRID3 152
#define WPITCH 272

__device__ float4 g_meta[NTOK];
__device__ int g_cnt[2][NEXP];
__device__ unsigned int g_etok[2][NEXP * NTOK];
__device__ float g_egat[2][NEXP * NTOK];

__device__ __forceinline__ uint32_t smem_u32(const void* p) {
    uint32_t a;
    asm("{ .reg .u64 t; cvta.to.shared.u64 t, %1; cvt.u32.u64 %0, t; }"
        : "=r"(a) : "l"(p));
    return a;
}

__device__ __forceinline__ uint32_t cvt_bf16x2(float hi, float lo) {
    uint32_t d;
    asm("cvt.rn.bf16x2.f32 %0, %1, %2;" : "=r"(d) : "f"(hi), "f"(lo));
    return d;
}

__device__ __forceinline__ void split2(float f0, float f1,
                                       uint32_t& hi, uint32_t& lo) {
    hi = cvt_bf16x2(f1, f0);
    float h0 = __uint_as_float(hi << 16);
    float h1 = __uint_as_float(hi & 0xffff0000u);
    lo = cvt_bf16x2(f1 - h1, f0 - h0);
}

__device__ __forceinline__ void ldsm_x2t(uint32_t& r0, uint32_t& r1, uint32_t a) {
    asm volatile("ldmatrix.sync.aligned.m8n8.x2.trans.shared.b16 {%0,%1}, [%2];"
                 : "=r"(r0), "=r"(r1) : "r"(a));
}

__device__ __forceinline__ void ldsm_x4(uint32_t& r0, uint32_t& r1,
                                        uint32_t& r2, uint32_t& r3, uint32_t a) {
    asm volatile("ldmatrix.sync.aligned.m8n8.x4.shared.b16 {%0,%1,%2,%3}, [%4];"
                 : "=r"(r0), "=r"(r1), "=r"(r2), "=r"(r3) : "r"(a));
}

__device__ __forceinline__ void mma16816(float* c,
                                         uint32_t a0, uint32_t a1, uint32_t a2,
                                         uint32_t a3, uint32_t b0, uint32_t b1) {
    asm volatile(
        "mma.sync.aligned.m16n8k16.row.col.f32.bf16.bf16.f32 "
        "{%0,%1,%2,%3}, {%4,%5,%6,%7}, {%8,%9}, {%0,%1,%2,%3};"
        : "+f"(c[0]), "+f"(c[1]), "+f"(c[2]), "+f"(c[3])
        : "r"(a0), "r"(a1), "r"(a2), "r"(a3), "r"(b0), "r"(b1));
}

__device__ __forceinline__ void cpa16(uint32_t dst, const void* src) {
    asm volatile("cp.async.cg.shared.global [%0], [%1], 16;"
                 :: "r"(dst), "l"(src) : "memory");
}

// ---------------- kernel 0: zero counters (graph replays!) ----------------
__global__ void k_zero() {
    if (threadIdx.x < 16) ((int*)g_cnt)[threadIdx.x] = 0;
}

// ---------------- kernel 1: gating + atomic slot allocation ----------------
#define G_SX   0
#define G_SWG  (128 * 132 * 4)
#define G_SMEM (G_SWG + HDIM * NEXP * 4)

extern __shared__ char smraw[];

__global__ void __launch_bounds__(128)
k_gate(const float* __restrict__ x, const float* __restrict__ wg) {
    float* sx  = (float*)(smraw + G_SX);
    float* swg = (float*)(smraw + G_SWG);
    __shared__ int wh0[4][8], wh1[4][8];
    __shared__ int gb0[8], gb1[8];

    const int tid = threadIdx.x, lane = tid & 31, w = tid >> 5;
    const int blk = blockIdx.x, tok0 = blk * 128;

    for (int i = tid; i < HDIM * NEXP; i += 128) swg[i] = wg[i];
    const float4* xg = (const float4*)(x + (size_t)tok0 * HDIM);
    for (int i = tid; i < 128 * 32; i += 128) {
        float4 v = xg[i];
        int t = i >> 5, c = (i & 31) * 4;
        *(float4*)(sx + t * 132 + c) = v;
    }
    __syncthreads();

    float lg[NEXP];
#pragma unroll
    for (int e = 0; e < NEXP; e++) lg[e] = 0.f;
    const float* xr = sx + tid * 132;
#pragma unroll 4
    for (int h4 = 0; h4 < 32; h4++) {
        float4 xq = *(const float4*)(xr + h4 * 4);
        const float* wr = swg + h4 * 32;
#pragma unroll
        for (int j = 0; j < 4; j++) {
            float xv = (j == 0) ? xq.x : (j == 1) ? xq.y : (j == 2) ? xq.z : xq.w;
            float4 wa = *(const float4*)(wr + j * 8);
            float4 wb = *(const float4*)(wr + j * 8 + 4);
            lg[0] = fmaf(xv, wa.x, lg[0]); lg[1] = fmaf(xv, wa.y, lg[1]);
            lg[2] = fmaf(xv, wa.z, lg[2]); lg[3] = fmaf(xv, wa.w, lg[3]);
            lg[4] = fmaf(xv, wb.x, lg[4]); lg[5] = fmaf(xv, wb.y, lg[5]);
            lg[6] = fmaf(xv, wb.z, lg[6]); lg[7] = fmaf(xv, wb.w, lg[7]);
        }
    }
    int i0 = 0; float v0 = lg[0];
#pragma unroll
    for (int e = 1; e < NEXP; e++)
        if (lg[e] > v0) { v0 = lg[e]; i0 = e; }
    int i1 = -1; float v1 = -3.4e38f;
#pragma unroll
    for (int e = 0; e < NEXP; e++)
        if (e != i0 && lg[e] > v1) { v1 = lg[e]; i1 = e; }
    float e1 = expf(v1 - v0);
    float g0 = 1.f / (1.f + e1);
    float g1 = e1 * g0;

    unsigned ltm = (1u << lane) - 1u;
    int myr0 = 0, myr1 = 0;
#pragma unroll
    for (int e = 0; e < NEXP; e++) {
        unsigned m0 = __ballot_sync(0xffffffffu, i0 == e);
        unsigned m1 = __ballot_sync(0xffffffffu, i1 == e);
        if (i0 == e) myr0 = __popc(m0 & ltm);
        if (i1 == e) myr1 = __popc(m1 & ltm);
        if (lane == e) { wh0[w][e] = __popc(m0); wh1[w][e] = __popc(m1); }
    }
    __syncthreads();
    int r0 = myr0, r1 = myr1;
    for (int ww = 0; ww < w; ww++) { r0 += wh0[ww][i0]; r1 += wh1[ww][i1]; }

    if (tid < NEXP) {
        int c0 = wh0[0][tid] + wh0[1][tid] + wh0[2][tid] + wh0[3][tid];
        int c1 = wh1[0][tid] + wh1[1][tid] + wh1[2][tid] + wh1[3][tid];
        gb0[tid] = atomicAdd(&g_cnt[0][tid], c0);
        gb1[tid] = atomicAdd(&g_cnt[1][tid], c1);
    }
    __syncthreads();

    int token = tok0 + tid;
    int s0 = gb0[i0] + r0, s1 = gb1[i1] + r1;
    g_etok[0][i0 * NTOK + s0] = (unsigned)token;
    g_egat[0][i0 * NTOK + s0] = g0;
    g_etok[1][i1 * NTOK + s1] = (unsigned)token;
    g_egat[1][i1 * NTOK + s1] = g1;
    g_meta[token] = make_float4(
        __uint_as_float((unsigned)i0 | ((unsigned)i1 << 8)), g0, g1, 0.f);
}

// ---------------- kernel 2: pipelined FFN GEMM (round-6 structure) ----------------
#define F_WHI   0
#define F_WLO   34816
#define F_AHI   69632
#define F_ALO   104448
#define F_STAGE 139264
#define F_BIAS  204800
#define F_TOK   208896
#define F_META  209408
#define F_SMEM  211456
#define NTHR_F 512

#define TILE_ELI(t, e_, li_) do { \
        e_ = 0; \
        _Pragma("unroll") \
        for (int k_ = 0; k_ < NEXP; k_++) if (tb[k_ + 1] <= (t)) e_ = k_ + 1; \
        li_ = (t) - tb[e_]; \
    } while (0)

__global__ void __launch_bounds__(NTHR_F, 1)
k_ffn(const float* __restrict__ x, const float* __restrict__ we,
      const float* __restrict__ be, float* __restrict__ out, int p) {
    const int tid = threadIdx.x, lane = tid & 31, w = tid >> 5;
    float* sbias = (float*)(smraw + F_BIAS);
    int* stok = (int*)(smraw + F_TOK);
    float4* smeta = (float4*)(smraw + F_META);
    const uint32_t su = smem_u32(smraw);

    const unsigned* tokl = g_etok[p];
    const float* gatel   = g_egat[p];

    int cnt[NEXP], tb[NEXP + 1];
    tb[0] = 0;
#pragma unroll
    for (int e = 0; e < NEXP; e++) {
        cnt[e] = g_cnt[p][e];
        tb[e + 1] = tb[e] + ((cnt[e] + 127) >> 7);
    }
    const int ntiles = tb[NEXP];
    const int t0 = (int)((long long)blockIdx.x * ntiles / GRID3);
    const int t1 = (int)((long long)(blockIdx.x + 1) * ntiles / GRID3);
    if (t0 >= t1) return;

    for (int i = tid; i < NEXP * ODIM; i += NTHR_F) sbias[i] = be[i];

    const int mt = w >> 2, nq = w & 3;
    const int grp = lane >> 3;
    const int ar = (lane & 7) + ((grp & 1) ? 8 : 0);
    const int ac = (grp >> 1) * 8;
    const uint32_t a_base0 = su + F_AHI
                           + (uint32_t)(mt * 32 + ar) * WPITCH + (uint32_t)ac * 2;
    const uint32_t a_base1 = a_base0 + 16u * WPITCH;
    const uint32_t b_base  = su + F_WHI + (uint32_t)(lane & 15) * WPITCH
                           + (uint32_t)nq * 64u;

    const int row = tid >> 2, q = tid & 3;
    const uint32_t stage_b = su + F_STAGE + (uint32_t)tid * 128u;
    char* stage_l = smraw + F_STAGE + tid * 128;

    // prologue: prefetch tile t0
    unsigned nx_token; float nx_gate;
    {
        int e_, li_;
        TILE_ELI(t0, e_, li_);
        int lb = e_ * NTOK + li_ * 128;
        int v0 = min(128, cnt[e_] - li_ * 128);
        nx_token = 0; nx_gate = 0.f;
        if (row < v0) { nx_token = tokl[lb + row]; nx_gate = gatel[lb + row]; }
        const char* src = (const char*)(x + (size_t)nx_token * HDIM + q * 32);
#pragma unroll
        for (int i = 0; i < 8; i++)
            cpa16(stage_b + (uint32_t)(((i + tid) & 7) * 16), src + i * 16);
        asm volatile("cp.async.commit_group;" ::: "memory");
    }

    int cur_e = -1;
    for (int t = t0; t < t1; t++) {
        int e, li;
        TILE_ELI(t, e, li);
        const int valid = min(128, cnt[e] - li * 128);
        const unsigned token = nx_token;
        const float gv = nx_gate;

        if (t + 1 < t1) {
            int en, lin;
            TILE_ELI(t + 1, en, lin);
            int lbn = en * NTOK + lin * 128;
            int vn = min(128, cnt[en] - lin * 128);
            nx_token = 0; nx_gate = 0.f;
            if (row < vn) { nx_token = tokl[lbn + row]; nx_gate = gatel[lbn + row]; }
        }

        __syncthreads();   // prev GEMM done: A & W writable

        if (e != cur_e) {
            const float4* wgl = (const float4*)(we + (size_t)e * HDIM * ODIM);
            for (int i = tid; i < HDIM * 32; i += NTHR_F) {
                float4 v = wgl[i];
                int h = i >> 5, o4 = (i & 31);
                uint32_t h0, l0, h1, l1;
                split2(v.x, v.y, h0, l0);
                split2(v.z, v.w, h1, l1);
                uint32_t off = (uint32_t)h * WPITCH + (uint32_t)o4 * 8;
                *(uint2*)(smraw + F_WHI + off) = make_uint2(h0, h1);
                *(uint2*)(smraw + F_WLO + off) = make_uint2(l0, l1);
            }
            cur_e = e;
        }

        // convert own staged 32 floats -> A hi/lo
        asm volatile("cp.async.wait_group 0;" ::: "memory");
        if (q == 0) {
            stok[row] = (int)token;
            if (p == 0) smeta[row] = g_meta[token];
        }
        {
            uint32_t abase = (uint32_t)row * WPITCH + (uint32_t)q * 64;
#pragma unroll
            for (int i = 0; i < 8; i++) {
                float4 v = *(const float4*)(stage_l + ((i + tid) & 7) * 16);
                uint32_t h0, l0, h1, l1;
                split2(gv * v.x, gv * v.y, h0, l0);
                split2(gv * v.z, gv * v.w, h1, l1);
                *(uint2*)(smraw + F_AHI + abase + i * 8) = make_uint2(h0, h1);
                *(uint2*)(smraw + F_ALO + abase + i * 8) = make_uint2(l0, l1);
            }
        }
        // prefetch t+1 x rows (overlaps GEMM)
        if (t + 1 < t1) {
            const char* src = (const char*)(x + (size_t)nx_token * HDIM + q * 32);
#pragma unroll
            for (int i = 0; i < 8; i++)
                cpa16(stage_b + (uint32_t)(((i + tid) & 7) * 16), src + i * 16);
        }
        asm volatile("cp.async.commit_group;" ::: "memory");
        __syncthreads();   // A ready

        // GEMM: 2 m16 x 4 n8 per warp, x2t B loads (round-6 proven)
        float acc[2][4][4], accB[2][4][4];
#pragma unroll
        for (int m = 0; m < 2; m++)
#pragma unroll
            for (int nt = 0; nt < 4; nt++)
#pragma unroll
                for (int j = 0; j < 4; j++) {
                    acc[m][nt][j] = 0.f; accB[m][nt][j] = 0.f;
                }

#pragma unroll
        for (int kb = 0; kb < 8; kb++) {
            uint32_t ah[2][4], al[2][4];
            uint32_t aa0 = a_base0 + (uint32_t)kb * 32;
            uint32_t aa1 = a_base1 + (uint32_t)kb * 32;
            ldsm_x4(ah[0][0], ah[0][1], ah[0][2], ah[0][3], aa0);
            ldsm_x4(al[0][0], al[0][1], al[0][2], al[0][3], aa0 + (F_ALO - F_AHI));
            ldsm_x4(ah[1][0], ah[1][1], ah[1][2], ah[1][3], aa1);
            ldsm_x4(al[1][0], al[1][1], al[1][2], al[1][3], aa1 + (F_ALO - F_AHI));
            uint32_t bb = b_base + (uint32_t)kb * 16 * WPITCH;
#pragma unroll
            for (int nt = 0; nt < 4; nt++) {
                uint32_t bh0, bh1, bl0, bl1;
                ldsm_x2t(bh0, bh1, bb + nt * 16);
                ldsm_x2t(bl0, bl1, bb + nt * 16 + (F_WLO - F_WHI));
#pragma unroll
                for (int m = 0; m < 2; m++) {
                    mma16816(acc[m][nt], ah[m][0], ah[m][1], ah[m][2], ah[m][3],
                             bh0, bh1);
                    mma16816(accB[m][nt], ah[m][0], ah[m][1], ah[m][2], ah[m][3],
                             bl0, bl1);
                    mma16816(accB[m][nt], al[m][0], al[m][1], al[m][2], al[m][3],
                             bh0, bh1);
                }
            }
        }

        // epilogue
        const int qr = lane >> 2, qk = (lane & 3) * 2;
#pragma unroll
        for (int m = 0; m < 2; m++) {
            int ra = mt * 32 + m * 16 + qr;
            int rb = ra + 8;
            bool va = ra < valid, vb = rb < valid;
            float* opa = va ? out + (size_t)stok[ra] * ODIM : 0;
            float* opb = vb ? out + (size_t)stok[rb] * ODIM : 0;
            if (p == 0) {
#pragma unroll
                for (int hrow = 0; hrow < 2; hrow++) {
                    int r = hrow ? rb : ra;
                    float* op = hrow ? opb : opa;
                    if (!(hrow ? vb : va)) continue;
                    float4 mm = smeta[r];
                    unsigned u = __float_as_uint(mm.x);
                    const float* b0p = sbias + (u & 0xff) * ODIM;
                    const float* b1p = sbias + ((u >> 8) & 0xff) * ODIM;
                    float gg0 = mm.y, gg1 = mm.z;
                    const int ci = hrow * 2;
#pragma unroll
                    for (int nt = 0; nt < 4; nt++) {
                        int col = nq * 32 + nt * 8 + qk;
                        float2 v;
                        v.x = acc[m][nt][ci] + accB[m][nt][ci]
                            + gg0 * b0p[col] + gg1 * b1p[col];
                        v.y = acc[m][nt][ci + 1] + accB[m][nt][ci + 1]
                            + gg0 * b0p[col + 1] + gg1 * b1p[col + 1];
                        *(float2*)(op + col) = v;
                    }
                }
            } else {
                float2 o[2][4];
#pragma unroll
                for (int nt = 0; nt < 4; nt++) {
                    int col = nq * 32 + nt * 8 + qk;
                    if (va) o[0][nt] = *(float2*)(opa + col);
                    if (vb) o[1][nt] = *(float2*)(opb + col);
                }
#pragma unroll
                for (int nt = 0; nt < 4; nt++) {
                    int col = nq * 32 + nt * 8 + qk;
                    if (va) {
                        float2 v = o[0][nt];
                        v.x += acc[m][nt][0] + accB[m][nt][0];
                        v.y += acc[m][nt][1] + accB[m][nt][1];
                        *(float2*)(opa + col) = v;
                    }
                    if (vb) {
                        float2 v = o[1][nt];
                        v.x += acc[m][nt][2] + accB[m][nt][2];
                        v.y += acc[m][nt][3] + accB[m][nt][3];
                        *(float2*)(opb + col) = v;
                    }
                }
            }
        }
    }
}

// ---------------- launch ----------------
extern "C" void kernel_launch(void* const* d_in, const int* in_sizes, int n_in,
                              void* d_out, int out_size) {
    const float* x  = (const float*)d_in[0];
    const float* wg = (const float*)d_in[1];
    // d_in[2] = w_noise (inactive in eval mode)
    const float* we = (const float*)d_in[3];
    const float* be = (const float*)d_in[4];
    float* out = (float*)d_out;

    cudaFuncSetAttribute(k_gate, cudaFuncAttributeMaxDynamicSharedMemorySize,
                         G_SMEM);
    cudaFuncSetAttribute(k_ffn, cudaFuncAttributeMaxDynamicSharedMemorySize,
                         F_SMEM);

    k_zero<<<1, 32>>>();
    k_gate<<<NBLK, 128, G_SMEM>>>(x, wg);
    k_ffn<<<GRID3, NTHR_F, F_SMEM>>>(x, we, be, out, 0);
    k_ffn<<<GRID3, NTHR_F, F_SMEM>>>(x, we, be, out, 1);
}